// round 2
// baseline (speedup 1.0000x reference)
#include <cuda_runtime.h>
#include <cstdint>

// ---------------------------------------------------------------------------
// Compile-time Cayley sign table for Cl(3,1,0), DIM = 16.
// Mirrors the reference Python blade_sign() exactly.
// For r=0 the product blade is always c = i ^ j and sign is +/-1.
// All helpers are __host__ __device__ constexpr so the table can be built as
// a local constexpr inside the kernel (no --expt-relaxed-constexpr needed).
// ---------------------------------------------------------------------------
namespace cl {

constexpr int NGEN = 4;
constexpr int DIM  = 16;
constexpr int PP   = 3;   // first 3 generators square to +1, 4th to -1

__host__ __device__ constexpr float metric_of(int b) {
    return b < PP ? 1.0f : -1.0f;
}

__host__ __device__ constexpr float blade_sign_of(int a_idx, int b_idx) {
    int result[NGEN] = {0, 0, 0, 0};
    int len = 0;
    for (int i = 0; i < NGEN; ++i)
        if ((a_idx >> i) & 1) result[len++] = i;
    float sign = 1.0f;
    for (int b = 0; b < NGEN; ++b) {
        if (!((b_idx >> b) & 1)) continue;
        int swaps = 0;
        bool removed = false;
        for (int i = len - 1; i >= 0; --i) {
            if (result[i] < b) break;
            if (result[i] == b) {
                sign *= metric_of(b);
                if (swaps & 1) sign = -sign;
                for (int k = i; k < len - 1; ++k) result[k] = result[k + 1];
                --len;
                removed = true;
                break;
            }
            ++swaps;
        }
        if (!removed) {
            if (swaps & 1) sign = -sign;
            int ins = len - swaps;
            for (int k = len; k > ins; --k) result[k] = result[k - 1];
            result[ins] = b;
            ++len;
        }
    }
    return sign;
}

struct Tables { float sign[DIM][DIM]; };

__host__ __device__ constexpr Tables make_tables() {
    Tables t{};
    for (int i = 0; i < DIM; ++i)
        for (int j = 0; j < DIM; ++j)
            t.sign[i][j] = blade_sign_of(i, j);
    return t;
}

} // namespace cl

// ---------------------------------------------------------------------------
// Kernel: one thread = one multivector row.
//   reads  16 floats of a, 16 floats of b  (4x float4 each)
//   does   256 FFMAs into 16 register accumulators (acc index folds: i^j)
//   writes 16 floats (4x float4), clamped to [-1000, 1000]
// Pure HBM-bound: 192 MB total traffic.
// ---------------------------------------------------------------------------
__global__ void __launch_bounds__(256)
clifford_mul_kernel(const float* __restrict__ a,
                    const float* __restrict__ b,
                    float* __restrict__ out,
                    int n_rows) {
    constexpr cl::Tables TBL = cl::make_tables();

    const int row = blockIdx.x * blockDim.x + threadIdx.x;
    if (row >= n_rows) return;

    const float4* a4 = reinterpret_cast<const float4*>(a) + (size_t)row * 4;
    const float4* b4 = reinterpret_cast<const float4*>(b) + (size_t)row * 4;

    float av[16], bv[16];
#pragma unroll
    for (int k = 0; k < 4; ++k) {
        float4 va = a4[k];
        av[4 * k + 0] = va.x; av[4 * k + 1] = va.y;
        av[4 * k + 2] = va.z; av[4 * k + 3] = va.w;
    }
#pragma unroll
    for (int k = 0; k < 4; ++k) {
        float4 vb = b4[k];
        bv[4 * k + 0] = vb.x; bv[4 * k + 1] = vb.y;
        bv[4 * k + 2] = vb.z; bv[4 * k + 3] = vb.w;
    }

    float acc[16];
#pragma unroll
    for (int c = 0; c < 16; ++c) acc[c] = 0.0f;

#pragma unroll
    for (int i = 0; i < 16; ++i) {
#pragma unroll
        for (int j = 0; j < 16; ++j) {
            // TBL.sign[i][j] is a compile-time constant after full unroll;
            // the branch resolves at compile time and the negation is a free
            // FFMA operand modifier in SASS.
            if (TBL.sign[i][j] > 0.0f) {
                acc[i ^ j] = fmaf(av[i], bv[j], acc[i ^ j]);
            } else {
                acc[i ^ j] = fmaf(-av[i], bv[j], acc[i ^ j]);
            }
        }
    }

    float4* o4 = reinterpret_cast<float4*>(out) + (size_t)row * 4;
#pragma unroll
    for (int k = 0; k < 4; ++k) {
        float4 v;
        v.x = fminf(fmaxf(acc[4 * k + 0], -1000.0f), 1000.0f);
        v.y = fminf(fmaxf(acc[4 * k + 1], -1000.0f), 1000.0f);
        v.z = fminf(fmaxf(acc[4 * k + 2], -1000.0f), 1000.0f);
        v.w = fminf(fmaxf(acc[4 * k + 3], -1000.0f), 1000.0f);
        o4[k] = v;
    }
}

extern "C" void kernel_launch(void* const* d_in, const int* in_sizes, int n_in,
                              void* d_out, int out_size) {
    const float* a = (const float*)d_in[0];
    const float* b = (const float*)d_in[1];
    float* out = (float*)d_out;

    const int n_rows = in_sizes[0] / 16;  // 1,048,576
    const int threads = 256;
    const int blocks = (n_rows + threads - 1) / threads;
    clifford_mul_kernel<<<blocks, threads>>>(a, b, out, n_rows);
}